// round 1
// baseline (speedup 1.0000x reference)
#include <cuda_runtime.h>

#define V_N  100000
#define B_N  8
#define FC_N 200000
#define U_N  1024
#define T_N  110000
#define K_N  2
#define EPS_F 1e-5f

// Scratch vertex normals, layout [V][B][4] floats (float4 per (v,b)), 12.8 MB.
__device__ float4 g_vn[V_N * B_N];

__global__ __launch_bounds__(256) void zero_vn_kernel() {
    int i = blockIdx.x * blockDim.x + threadIdx.x;
    if (i < V_N * B_N) g_vn[i] = make_float4(0.f, 0.f, 0.f, 0.f);
}

// One thread per (face, batch); b fastest so 8 lanes share vi[f].
__global__ __launch_bounds__(256) void face_pass_kernel(
    const float* __restrict__ verts, const int* __restrict__ vi)
{
    int tid = blockIdx.x * blockDim.x + threadIdx.x;
    if (tid >= FC_N * B_N) return;
    int f = tid >> 3;
    int b = tid & 7;

    int i0 = __ldg(&vi[f * 3 + 0]);
    int i1 = __ldg(&vi[f * 3 + 1]);
    int i2 = __ldg(&vi[f * 3 + 2]);

    const float* vb = verts + (size_t)b * (V_N * 3);
    float ax = __ldg(&vb[i0 * 3 + 0]), ay = __ldg(&vb[i0 * 3 + 1]), az = __ldg(&vb[i0 * 3 + 2]);
    float bx = __ldg(&vb[i1 * 3 + 0]), by = __ldg(&vb[i1 * 3 + 1]), bz = __ldg(&vb[i1 * 3 + 2]);
    float cx = __ldg(&vb[i2 * 3 + 0]), cy = __ldg(&vb[i2 * 3 + 1]), cz = __ldg(&vb[i2 * 3 + 2]);

    float e1x = bx - ax, e1y = by - ay, e1z = bz - az;
    float e2x = cx - ax, e2y = cy - ay, e2z = cz - az;
    float nx = e1y * e2z - e1z * e2y;
    float ny = e1z * e2x - e1x * e2z;
    float nz = e1x * e2y - e1y * e2x;

    float nrm = sqrtf(nx * nx + ny * ny + nz * nz);
    if (nrm >= EPS_F) {
        float inv = 1.f / nrm;
        nx *= inv; ny *= inv; nz *= inv;
    }

    float* d0 = (float*)&g_vn[i0 * B_N + b];
    atomicAdd(d0 + 0, nx); atomicAdd(d0 + 1, ny); atomicAdd(d0 + 2, nz);
    float* d1 = (float*)&g_vn[i1 * B_N + b];
    atomicAdd(d1 + 0, nx); atomicAdd(d1 + 1, ny); atomicAdd(d1 + 2, nz);
    float* d2 = (float*)&g_vn[i2 * B_N + b];
    atomicAdd(d2 + 0, nx); atomicAdd(d2 + 1, ny); atomicAdd(d2 + 2, nz);
}

__global__ __launch_bounds__(256) void norm_vn_kernel() {
    int i = blockIdx.x * blockDim.x + threadIdx.x;
    if (i >= V_N * B_N) return;
    float4 v = g_vn[i];
    float nrm = sqrtf(v.x * v.x + v.y * v.y + v.z * v.z);
    if (nrm >= EPS_F) {
        float inv = 1.f / nrm;
        v.x *= inv; v.y *= inv; v.z *= inv;
    }
    v.w = 0.f;
    g_vn[i] = v;
}

// One thread per (vertex, batch); b fastest (8 lanes of a vertex share all
// pixel-data loads). 32 vertices per 256-thread block. Output transposed
// through smem for coalesced [B][V][3] stores.
__global__ __launch_bounds__(256) void sample_pass_kernel(
    const float* __restrict__ bary,
    const float* __restrict__ vt,
    const int*   __restrict__ idximg,
    const int*   __restrict__ v2uv,
    float*       __restrict__ out)
{
    __shared__ float s[32 * B_N * 3];  // [b][vloc*3+c] = s[b*96 + vloc*3 + c]

    int local = threadIdx.x;
    int vloc  = local >> 3;
    int b     = local & 7;
    int v     = blockIdx.x * 32 + vloc;

    float accx = 0.f, accy = 0.f, accz = 0.f;

    if (v < V_N) {
        #pragma unroll
        for (int k = 0; k < K_N; k++) {
            int t = __ldg(&v2uv[v * K_N + k]);
            float u  = __ldg(&vt[t * 2 + 0]);
            float wv = __ldg(&vt[t * 2 + 1]);

            // ix = ((2u-1 + 1)*W - 1)*0.5 = u*W - 0.5
            float ix = u  * (float)U_N - 0.5f;
            float iy = wv * (float)U_N - 0.5f;
            float x0f = floorf(ix), y0f = floorf(iy);
            int x0 = (int)x0f, y0 = (int)y0f;
            float wx1 = ix - x0f, wx0 = 1.f - wx1;
            float wy1 = iy - y0f, wy0 = 1.f - wy1;

            #pragma unroll
            for (int tap = 0; tap < 4; tap++) {
                int xi = x0 + (tap & 1);
                int yi = y0 + (tap >> 1);
                float wt = ((tap & 1) ? wx1 : wx0) * ((tap >> 1) ? wy1 : wy0);
                if (xi < 0 || xi >= U_N || yi < 0 || yi >= U_N) continue;
                int pix = yi * U_N + xi;

                int j0 = __ldg(&idximg[pix * 3 + 0]);
                int j1 = __ldg(&idximg[pix * 3 + 1]);
                int j2 = __ldg(&idximg[pix * 3 + 2]);
                if (j0 == -1 || j1 == -1 || j2 == -1) continue;  // mask
                j0 = min(max(j0, 0), V_N - 1);
                j1 = min(max(j1, 0), V_N - 1);
                j2 = min(max(j2, 0), V_N - 1);

                float b0 = __ldg(&bary[pix * 3 + 0]);
                float b1 = __ldg(&bary[pix * 3 + 1]);
                float b2 = __ldg(&bary[pix * 3 + 2]);

                float4 n0 = g_vn[j0 * B_N + b];
                float4 n1 = g_vn[j1 * B_N + b];
                float4 n2 = g_vn[j2 * B_N + b];

                accx += wt * (b0 * n0.x + b1 * n1.x + b2 * n2.x);
                accy += wt * (b0 * n0.y + b1 * n1.y + b2 * n2.y);
                accz += wt * (b0 * n0.z + b1 * n1.z + b2 * n2.z);
            }
        }
    }

    // mean over K
    float sc = 1.f / (float)K_N;
    s[b * 96 + vloc * 3 + 0] = accx * sc;
    s[b * 96 + vloc * 3 + 1] = accy * sc;
    s[b * 96 + vloc * 3 + 2] = accz * sc;
    __syncthreads();

    // Coalesced write-out: out[b][v][c], 768 floats per block.
    int v0 = blockIdx.x * 32;
    for (int i = local; i < 32 * B_N * 3; i += 256) {
        int bb = i / 96;
        int r  = i - bb * 96;           // vl*3 + c
        int vv = v0 + r / 3;
        if (vv < V_N) out[(size_t)bb * (V_N * 3) + (size_t)v0 * 3 + r] = s[i];
    }
}

extern "C" void kernel_launch(void* const* d_in, const int* in_sizes, int n_in,
                              void* d_out, int out_size)
{
    const float* verts  = (const float*)d_in[0];  // [B, V, 3]
    const float* bary   = (const float*)d_in[1];  // [U, U, 3]
    const float* vt     = (const float*)d_in[2];  // [T, 2]
    const int*   vi     = (const int*)  d_in[3];  // [Fc, 3]
    const int*   idximg = (const int*)  d_in[4];  // [U, U, 3]
    const int*   v2uv   = (const int*)  d_in[5];  // [V, K]
    float*       out    = (float*)d_out;          // [B, V, 3]

    (void)in_sizes; (void)n_in; (void)out_size;

    zero_vn_kernel<<<(V_N * B_N + 255) / 256, 256>>>();
    face_pass_kernel<<<(FC_N * B_N + 255) / 256, 256>>>(verts, vi);
    norm_vn_kernel<<<(V_N * B_N + 255) / 256, 256>>>();
    sample_pass_kernel<<<(V_N + 31) / 32, 256>>>(bary, vt, idximg, v2uv, out);
}